// round 7
// baseline (speedup 1.0000x reference)
#include <cuda_runtime.h>

// MeshfreeKANNet: u[m] = (sum_n phi_win[m,n]*w[n]) / (sum_n phi_win[m,n] + 1e-10)
// Warp per point: ballot-compaction of in-radius (~7%) nodes, dense KAN eval.
// R6: (a) bit-exact sparse layer-2 — hat basis has support {jh, jh+1}; zero
//     terms satisfy fmaf(0,w,phi)==phi exactly, so skipping them is an
//     identity as long as kept terms use the unchanged reference formula and
//     the (h asc, s asc) accumulation order (contiguous support => preserved).
//     floor() selects WHICH terms to evaluate; never computes basis values
//     (the R3 failure mode).
// (b) 5 blocks/SM occupancy target, (c) float2 node loads in phase 1.

#define MM      4096
#define NN      1024
#define HIDN    8
#define WARPS   8
#define THREADS 256
#define BLOCKS  (MM / WARPS)

#define R2_F     0.09f
#define INV_R    (1.0f / 0.3f)
#define INV_H    (1.0f / 0.75f)

__global__ __launch_bounds__(THREADS, 5)
void meshfree_kan_kernel(const float* __restrict__ x,
                         const float* __restrict__ nodes,
                         const float* __restrict__ W1a,
                         const float* __restrict__ W1b,
                         const float* __restrict__ W2,
                         const float* __restrict__ w,
                         float* __restrict__ out)
{
    __shared__ float2 s_nxy[NN];
    __shared__ float  s_w[NN];
    // Packed layer-1 weights: s_Wp[h] = {W1a[h][0..4], W1b[h][0..4], pad, pad}
    __shared__ float4 s_Wp[HIDN][3];
    __shared__ float  s_W2[HIDN * 5];          // scalar, indexed by jh
    __shared__ unsigned short s_buf[WARPS][NN];

    const int tid = threadIdx.x;

    for (int i = tid; i < NN; i += THREADS) {
        s_nxy[i] = ((const float2*)nodes)[i];
        s_w[i]   = w[i];
    }
    if (tid < HIDN * 12) {
        const int h = tid / 12;
        const int e = tid % 12;
        float v = 0.0f;
        if (e < 5)       v = W1a[h * 5 + e];
        else if (e < 10) v = W1b[h * 5 + (e - 5)];
        ((float*)s_Wp)[tid] = v;
    }
    if (tid < HIDN * 5) s_W2[tid] = W2[tid];
    __syncthreads();

    const int warp = tid >> 5;
    const int lane = tid & 31;
    const int m = blockIdx.x * WARPS + warp;

    const float px = x[2 * m];
    const float py = x[2 * m + 1];

    const float gridv[5] = {-1.5f, -0.75f, 0.0f, 0.75f, 1.5f};

    // ---- Phase 1: distance filter + warp stream compaction ----
    int cnt = 0;
    const unsigned lmask = (1u << lane) - 1u;
    #pragma unroll 4
    for (int base = 0; base < NN; base += 32) {
        const int n = base + lane;
        const float2 nd = s_nxy[n];
        const float dx = px - nd.x;
        const float dy = py - nd.y;
        const float d2 = fmaf(dx, dx, dy * dy);
        const bool hit = (d2 <= R2_F);
        const unsigned msk = __ballot_sync(0xffffffffu, hit);
        if (hit) s_buf[warp][cnt + __popc(msk & lmask)] = (unsigned short)n;
        cnt += __popc(msk);
    }
    __syncwarp();

    // ---- Phase 2: KAN evaluation over compacted nodes ----
    float S = 0.0f, Sw = 0.0f;
    for (int i = lane; i < cnt; i += 32) {
        const int n = (int)s_buf[warp][i];
        const float2 nd = s_nxy[n];
        const float dx = px - nd.x;
        const float dy = py - nd.y;
        const float d2 = fmaf(dx, dx, dy * dy);
        const float kx = dx * INV_R;
        const float ky = dy * INV_R;

        // hat basis of the two KAN inputs (reference formulation, bit-exact)
        float ba[5], bb[5];
        #pragma unroll
        for (int s = 0; s < 5; s++) {
            ba[s] = fmaxf(0.0f, 1.0f - fabsf(kx - gridv[s]) * INV_H);
            bb[s] = fmaxf(0.0f, 1.0f - fabsf(ky - gridv[s]) * INV_H);
        }

        float phi_raw = 0.0f;
        #pragma unroll 2
        for (int h = 0; h < HIDN; h++) {
            const float4 q0 = s_Wp[h][0];
            const float4 q1 = s_Wp[h][1];
            const float4 q2 = s_Wp[h][2];
            const float wa[5] = {q0.x, q0.y, q0.z, q0.w, q1.x};
            const float wb[5] = {q1.y, q1.z, q1.w, q2.x, q2.y};

            // layer 1: same interleaved FMA chain order as R4/R5 (bit-exact)
            float hv = 0.0f;
            #pragma unroll
            for (int s = 0; s < 5; s++) {
                hv = fmaf(ba[s], wa[s], hv);
                hv = fmaf(bb[s], wb[s], hv);
            }

            // layer 2, sparse: support is {jh, jh+1}; kept terms use the
            // exact reference formula, order (s ascending) preserved.
            const int jh = __float2int_rd(fmaf(hv, INV_H, 2.0f));
            if ((unsigned)jh <= 4u) {
                const float g  = fmaf(0.75f, (float)jh, -1.5f);   // exact
                const float bh = fmaxf(0.0f, 1.0f - fabsf(hv - g) * INV_H);
                phi_raw = fmaf(bh, s_W2[h * 5 + jh], phi_raw);
            }
            const int j1 = jh + 1;
            if ((unsigned)j1 <= 4u) {
                const float g  = fmaf(0.75f, (float)j1, -1.5f);   // exact
                const float bh = fmaxf(0.0f, 1.0f - fabsf(hv - g) * INV_H);
                phi_raw = fmaf(bh, s_W2[h * 5 + j1], phi_raw);
            }
        }

        // cubic window: 1 - 6q^2 + 8q^3 - 3q^4
        const float q = sqrtf(d2) * INV_R;
        const float win = fmaf(q * q, fmaf(fmaf(-3.0f, q, 8.0f), q, -6.0f), 1.0f);

        const float phi = phi_raw * win;
        S  += phi;
        Sw  = fmaf(phi, s_w[n], Sw);
    }

    // ---- Warp reduction + normalize ----
    #pragma unroll
    for (int o = 16; o > 0; o >>= 1) {
        S  += __shfl_xor_sync(0xffffffffu, S,  o);
        Sw += __shfl_xor_sync(0xffffffffu, Sw, o);
    }
    if (lane == 0) out[m] = Sw / (S + 1e-10f);
}

extern "C" void kernel_launch(void* const* d_in, const int* in_sizes, int n_in,
                              void* d_out, int out_size)
{
    const float* x     = (const float*)d_in[0];   // [4096, 2]
    const float* nodes = (const float*)d_in[1];   // [1024, 2]
    const float* W1a   = (const float*)d_in[2];   // [8, 5]
    const float* W1b   = (const float*)d_in[3];   // [8, 5]
    const float* W2    = (const float*)d_in[4];   // [1, 40]
    const float* w     = (const float*)d_in[5];   // [1024, 1]
    float* out = (float*)d_out;                   // [4096, 1]

    meshfree_kan_kernel<<<BLOCKS, THREADS>>>(x, nodes, W1a, W1b, W2, w, out);
}